// round 14
// baseline (speedup 1.0000x reference)
#include <cuda_runtime.h>
#include <cuda_bf16.h>
#include <mma.h>
#include <cstdint>

using namespace nvcuda;

// Problem constants
#define NN 50000
#define EE 800000
#define FIN 256
#define H1 256
#define H2 256
#define H3 512
#define GG 512
#define FP 2048
#define NPART 98         // ceil(NN/512)

// ---------------- device scratch ----------------
__device__ float g_x[NN * H3];
__device__ float g_h[NN * H3];
__device__ float g_feats[GG * 2 * H3];
__device__ float g_dis[NN];
__device__ float g_gate[NN];
__device__ int   g_s32[EE];
__device__ int   g_d32[EE];
__device__ int   g_bat[NN];
__device__ int   g_ei_is64;
__device__ int   g_b_is64;
__device__ int   g_rowptr[NN + 1];
__device__ int   g_cursor[NN];
__device__ int   g_ecnt[NN];
__device__ int   g_tmp[NN];
__device__ int   g_part[128];
__device__ int   g_csrc[EE];
__device__ float g_cnorm[EE];
__device__ int   g_gcnt[GG];
__device__ int   g_gptr[GG + 1];
// bf16 hi/lo split of the current GEMM input (K=256 always)
__device__ __nv_bfloat16 g_bh[NN * FIN];
__device__ __nv_bfloat16 g_bl[NN * FIN];
// stacked split weights: rows [0,256)=Wh, [256,512)=Wl, [512,768)=Wh
__device__ __nv_bfloat16 g_wst1[768 * H1];
__device__ __nv_bfloat16 g_wst2[768 * H2];
__device__ __nv_bfloat16 g_wst3[768 * H3];

__device__ __forceinline__ float* selbuf(int s) {
    switch (s) { case 0: return g_x; case 1: return g_h; default: return g_feats; }
}
__device__ __forceinline__ const __nv_bfloat16* selwst(int s) {
    switch (s) { case 1: return g_wst1; case 2: return g_wst2; default: return g_wst3; }
}
__device__ __forceinline__ int clampi(int v, int lo, int hi) {
    return v < lo ? lo : (v > hi ? hi : v);
}

// ---------------- dtype detection ----------------
__global__ void k_detect(const void* ei, const void* batch) {
    if (threadIdx.x != 0 || blockIdx.x != 0) return;
    const long long* e64 = (const long long*)ei;
    int ok = 1;
    for (int i = 0; i < 16; i++) { long long v = e64[i]; if (v < 0 || v >= NN) ok = 0; }
    g_ei_is64 = ok;
    const long long* b64 = (const long long*)batch;
    int okb = 1;
    for (int i = 0; i < 16; i++) { long long v = b64[NN/2 - 16 + i]; if (v < 0 || v >= GG) okb = 0; }
    g_b_is64 = okb;
}
__device__ __forceinline__ int load_edge(const void* ei, int idx) {
    if (g_ei_is64) return clampi((int)((const long long*)ei)[idx], 0, NN - 1);
    return clampi(((const int*)ei)[idx], 0, NN - 1);
}

// ---------------- bf16 split setup ----------------
__global__ void k_xsplit(const float* __restrict__ x0) {
    int i = blockIdx.x * blockDim.x + threadIdx.x;
    if (i >= NN * FIN) return;
    float x = x0[i];
    __nv_bfloat16 h = __float2bfloat16(x);
    g_bh[i] = h;
    g_bl[i] = __float2bfloat16(x - __bfloat162float(h));
}
__global__ void k_wstack(const float* __restrict__ W1, const float* __restrict__ W2,
                         const float* __restrict__ W3) {
    int i = blockIdx.x * blockDim.x + threadIdx.x;
    const float* W; __nv_bfloat16* D; int Nc;
    if (i < 65536)       { W = W1; D = g_wst1; Nc = H1; }
    else if (i < 131072) { W = W2; D = g_wst2; Nc = H2; i -= 65536; }
    else if (i < 262144) { W = W3; D = g_wst3; Nc = H3; i -= 131072; }
    else return;
    int k = i / Nc, n = i % Nc;
    float x = W[(size_t)k * Nc + n];
    __nv_bfloat16 h = __float2bfloat16(x);
    __nv_bfloat16 l = __float2bfloat16(x - __bfloat162float(h));
    D[(size_t)k * Nc + n] = h;
    D[(size_t)(256 + k) * Nc + n] = l;
    D[(size_t)(512 + k) * Nc + n] = h;
}

// ---------------- precompute ----------------
__global__ void k_zero_cnt() {
    int i = blockIdx.x * blockDim.x + threadIdx.x;
    if (i < NN) g_ecnt[i] = 0;
    if (i < GG) g_gcnt[i] = 0;
}
__global__ void k_decode_hist(const void* ei, const void* batch) {
    int i = blockIdx.x * blockDim.x + threadIdx.x;
    if (i < EE) {
        int s = load_edge(ei, i);
        int d = load_edge(ei, EE + i);
        g_s32[i] = s;
        g_d32[i] = d;
        atomicAdd(&g_ecnt[d], 1);
    }
    if (i < NN) {
        int g = g_b_is64 ? (int)((const long long*)batch)[i] : ((const int*)batch)[i];
        g = clampi(g, 0, GG - 1);
        g_bat[i] = g;
        atomicAdd(&g_gcnt[g], 1);
    }
}
__global__ void k_scanA() {
    __shared__ int wsum[16];
    int b = blockIdx.x, t = threadIdx.x;
    int i = b * 512 + t;
    int v = (i < NN) ? g_ecnt[i] : 0;
    int lane = t & 31, wid = t >> 5;
    int x = v;
#pragma unroll
    for (int o = 1; o < 32; o <<= 1) { int y = __shfl_up_sync(~0u, x, o); if (lane >= o) x += y; }
    if (lane == 31) wsum[wid] = x;
    __syncthreads();
    if (wid == 0) {
        int s = (lane < 16) ? wsum[lane] : 0;
#pragma unroll
        for (int o = 1; o < 16; o <<= 1) { int y = __shfl_up_sync(~0u, s, o); if (lane >= o) s += y; }
        if (lane < 16) wsum[lane] = s;
    }
    __syncthreads();
    int incl = x + (wid ? wsum[wid - 1] : 0);
    if (i < NN) g_tmp[i] = incl;
    if (t == 511) g_part[b] = incl;
}
__global__ void k_scanB() {
    __shared__ int ws[4];
    int t = threadIdx.x;
    int v = (t < NPART) ? g_part[t] : 0;
    int lane = t & 31, wid = t >> 5;
    int x = v;
#pragma unroll
    for (int o = 1; o < 32; o <<= 1) { int y = __shfl_up_sync(~0u, x, o); if (lane >= o) x += y; }
    if (lane == 31) ws[wid] = x;
    __syncthreads();
    if (t == 0) { int a = 0; for (int w = 0; w < 4; w++) { int tm = ws[w]; ws[w] = a; a += tm; } }
    __syncthreads();
    x += ws[wid];
    if (t < NPART) g_part[t] = x - v;
}
__global__ void k_scanC() {
    int i = blockIdx.x * blockDim.x + threadIdx.x;
    if (i >= NN) return;
    int incl = g_tmp[i] + g_part[i >> 9];
    g_rowptr[i + 1] = incl;
    int cnt = g_ecnt[i];
    g_cursor[i] = incl - cnt;
    if (i == 0) g_rowptr[0] = 0;
    g_dis[i] = rsqrtf((float)(cnt + 1));
}
__global__ void k_norm_fill() {
    int e = blockIdx.x * blockDim.x + threadIdx.x;
    if (e >= EE) return;
    int s = g_s32[e], d = g_d32[e];
    int pos = atomicAdd(&g_cursor[d], 1);
    g_csrc[pos] = s;
    g_cnorm[pos] = g_dis[s] * g_dis[d];
}
__global__ void k_gscan() {
    __shared__ int sh[GG];
    int tid = threadIdx.x;
    sh[tid] = g_gcnt[tid];
    __syncthreads();
    for (int off = 1; off < GG; off <<= 1) {
        int t = (tid >= off) ? sh[tid - off] : 0;
        __syncthreads();
        sh[tid] += t;
        __syncthreads();
    }
    g_gptr[tid + 1] = sh[tid];
    if (tid == 0) g_gptr[0] = 0;
}

// ---------------- wmma bf16x3 GEMM, 64x64 warp tiles ----------------
// C[M,Nc] fp32 = split-K: [Ah|Ah|Al](M x 768) @ [Wh;Wl;Wh](768 x Nc),
// dropping Al*Wl (error ~2^-16 relative).
// 128x128 block tile, BK=32, 128 threads (4 warps, 2x2), warp tile 64x64:
// per ki-step 8 fragment loads -> 16 MMAs (2.0 MMA/load vs 1.33 before).
#define ALD 48     // A smem row pad (96B, 16B-multiple)
#define BLD 144    // B smem row pad (288B, 16B-multiple)

__global__ void __launch_bounds__(128)
wgemm(int w_sel, int c_sel, int M, int Nc) {
    const __nv_bfloat16* Wst = selwst(w_sel);
    float* C = selbuf(c_sel);
    __shared__ __nv_bfloat16 As[2][128][ALD];
    __shared__ __nv_bfloat16 Bs[2][32][BLD];
    const int tid = threadIdx.x;
    const int wid = tid >> 5;
    const int wm = wid & 1, wn = wid >> 1;     // 2 x 2 warp grid, 64x64 each
    const int bm = blockIdx.y * 128, bn = blockIdx.x * 128;

    wmma::fragment<wmma::accumulator, 16, 16, 16, float> acc[4][4];
#pragma unroll
    for (int mi = 0; mi < 4; mi++)
#pragma unroll
        for (int ni = 0; ni < 4; ni++) wmma::fill_fragment(acc[mi][ni], 0.0f);

    // A tile 128x32: one row per thread (32 bf16 = 4 uint4)
    const int ar = tid;
    const int gm = bm + ar;
    // B tile 32x128: row = tid>>2, 32-elem chunk = (tid&3)*32
    const int wr = tid >> 2, wc = (tid & 3) * 32;

    auto load_tiles = [&](int b, int kb) {
        // kb<16 -> Ah (vs Wh then Wl), kb>=16 -> Al (vs Wh). A col = (kb&7)*32.
        const __nv_bfloat16* Asrc = (kb < 16) ? g_bh : g_bl;
        int ka = (kb & 7) * 32;
        uint4 av[4] = {make_uint4(0,0,0,0), make_uint4(0,0,0,0),
                       make_uint4(0,0,0,0), make_uint4(0,0,0,0)};
        if (gm < M) {
            const __nv_bfloat16* ap = Asrc + (size_t)gm * FIN + ka;
#pragma unroll
            for (int q = 0; q < 4; q++) av[q] = *(const uint4*)(ap + q * 8);
        }
#pragma unroll
        for (int q = 0; q < 4; q++) *(uint4*)&As[b][ar][q * 8] = av[q];
        const __nv_bfloat16* wp = Wst + (size_t)(kb * 32 + wr) * Nc + bn + wc;
#pragma unroll
        for (int q = 0; q < 4; q++)
            *(uint4*)&Bs[b][wr][wc + q * 8] = *(const uint4*)(wp + q * 8);
    };

    load_tiles(0, 0);
    __syncthreads();

#pragma unroll 1
    for (int kb = 0; kb < 24; kb++) {
        int b = kb & 1;
        if (kb + 1 < 24) load_tiles((kb + 1) & 1, kb + 1);
#pragma unroll
        for (int ki = 0; ki < 2; ki++) {
            wmma::fragment<wmma::matrix_a, 16, 16, 16, __nv_bfloat16, wmma::row_major> af[4];
            wmma::fragment<wmma::matrix_b, 16, 16, 16, __nv_bfloat16, wmma::row_major> bfr[4];
#pragma unroll
            for (int mi = 0; mi < 4; mi++)
                wmma::load_matrix_sync(af[mi], &As[b][wm * 64 + mi * 16][ki * 16], ALD);
#pragma unroll
            for (int ni = 0; ni < 4; ni++)
                wmma::load_matrix_sync(bfr[ni], &Bs[b][ki * 16][wn * 64 + ni * 16], BLD);
#pragma unroll
            for (int mi = 0; mi < 4; mi++)
#pragma unroll
                for (int ni = 0; ni < 4; ni++)
                    wmma::mma_sync(acc[mi][ni], af[mi], bfr[ni], acc[mi][ni]);
        }
        __syncthreads();
    }

#pragma unroll
    for (int mi = 0; mi < 4; mi++) {
        int row = bm + wm * 64 + mi * 16;
        if (row + 16 > M) continue;     // M % 16 == 0 -> frag-granular guard exact
#pragma unroll
        for (int ni = 0; ni < 4; ni++) {
            int col = bn + wn * 64 + ni * 16;
            wmma::store_matrix_sync(C + (size_t)row * Nc + col, acc[mi][ni], Nc,
                                    wmma::mem_row_major);
        }
    }
}

// g_x = relu(g_x + b)  (post-GEMM3 epilogue)
__global__ void k_bias_relu(const float* __restrict__ b) {
    int i = blockIdx.x * blockDim.x + threadIdx.x;
    if (i < NN * H3) g_x[i] = fmaxf(g_x[i] + b[i & (H3 - 1)], 0.0f);
}

// ---------------- fp32 SGEMM (head) with fma.rn.f32x2 ----------------
#define TBN 128
#define TBK 16
template <int BMv, bool BIAS_RELU>
__global__ void __launch_bounds__(256)
sgemm128(const float* __restrict__ Aext, int a_sel,
         const float* __restrict__ W, const float* __restrict__ bias,
         float* __restrict__ Cext, int c_sel, int M, int K, int Nc) {
    constexpr int RM = BMv / 16;
    constexpr int AL = BMv / 64;
    const float* A = (a_sel < 0) ? Aext : selbuf(a_sel);
    float* C = (c_sel < 0) ? Cext : selbuf(c_sel);
    __shared__ float As2[TBK][BMv + 4];
    __shared__ float Ws2[TBK][TBN + 4];
    const int tid = threadIdx.x;
    const int tx = tid & 15, ty = tid >> 4;
    const int bm = blockIdx.y * BMv, bn = blockIdx.x * TBN;
    float4 pa[AL], pw[2];
    unsigned long long acc[RM][4];
#pragma unroll
    for (int i = 0; i < RM; i++)
#pragma unroll
        for (int j = 0; j < 4; j++) acc[i][j] = 0ull;
#pragma unroll
    for (int i = 0; i < AL; i++) {
        int idx = tid + i * 256;
        int m = idx >> 2, kq = idx & 3;
        int gm = bm + m;
        pa[i] = (gm < M) ? *(const float4*)(A + (size_t)gm * K + kq * 4)
                         : make_float4(0.f, 0.f, 0.f, 0.f);
    }
#pragma unroll
    for (int i = 0; i < 2; i++) {
        int idx = tid + i * 256;
        int kk = idx >> 5, nq = idx & 31;
        pw[i] = *(const float4*)(W + (size_t)kk * Nc + bn + nq * 4);
    }
    for (int k0 = 0; k0 < K; k0 += TBK) {
#pragma unroll
        for (int i = 0; i < AL; i++) {
            int idx = tid + i * 256;
            int m = idx >> 2, kq = idx & 3;
            As2[kq * 4 + 0][m] = pa[i].x; As2[kq * 4 + 1][m] = pa[i].y;
            As2[kq * 4 + 2][m] = pa[i].z; As2[kq * 4 + 3][m] = pa[i].w;
        }
#pragma unroll
        for (int i = 0; i < 2; i++) {
            int idx = tid + i * 256;
            int kk = idx >> 5, nq = idx & 31;
            *(float4*)&Ws2[kk][nq * 4] = pw[i];
        }
        __syncthreads();
        if (k0 + TBK < K) {
            int k1 = k0 + TBK;
#pragma unroll
            for (int i = 0; i < AL; i++) {
                int idx = tid + i * 256;
                int m = idx >> 2, kq = idx & 3;
                int gm = bm + m;
                pa[i] = (gm < M) ? *(const float4*)(A + (size_t)gm * K + k1 + kq * 4)
                                 : make_float4(0.f, 0.f, 0.f, 0.f);
            }
#pragma unroll
            for (int i = 0; i < 2; i++) {
                int idx = tid + i * 256;
                int kk = idx >> 5, nq = idx & 31;
                pw[i] = *(const float4*)(W + (size_t)(k1 + kk) * Nc + bn + nq * 4);
            }
        }
#pragma unroll
        for (int kk = 0; kk < TBK; kk++) {
            float a8[RM];
#pragma unroll
            for (int q = 0; q < RM / 4; q++) {
                float4 af = *(const float4*)&As2[kk][ty * RM + q * 4];
                a8[q * 4 + 0] = af.x; a8[q * 4 + 1] = af.y;
                a8[q * 4 + 2] = af.z; a8[q * 4 + 3] = af.w;
            }
            unsigned long long a2[RM];
#pragma unroll
            for (int i = 0; i < RM; i++) {
                unsigned int ab = __float_as_uint(a8[i]);
                asm("mov.b64 %0, {%1, %1};" : "=l"(a2[i]) : "r"(ab));
            }
            float4 wf0 = *(const float4*)&Ws2[kk][tx * 8];
            float4 wf1 = *(const float4*)&Ws2[kk][tx * 8 + 4];
            unsigned long long w2[4];
            asm("mov.b64 %0, {%1, %2};" : "=l"(w2[0]) : "r"(__float_as_uint(wf0.x)), "r"(__float_as_uint(wf0.y)));
            asm("mov.b64 %0, {%1, %2};" : "=l"(w2[1]) : "r"(__float_as_uint(wf0.z)), "r"(__float_as_uint(wf0.w)));
            asm("mov.b64 %0, {%1, %2};" : "=l"(w2[2]) : "r"(__float_as_uint(wf1.x)), "r"(__float_as_uint(wf1.y)));
            asm("mov.b64 %0, {%1, %2};" : "=l"(w2[3]) : "r"(__float_as_uint(wf1.z)), "r"(__float_as_uint(wf1.w)));
#pragma unroll
            for (int i = 0; i < RM; i++)
#pragma unroll
                for (int j = 0; j < 4; j++)
                    asm("fma.rn.f32x2 %0, %1, %2, %3;"
                        : "=l"(acc[i][j]) : "l"(a2[i]), "l"(w2[j]), "l"(acc[i][j]));
        }
        __syncthreads();
    }
#pragma unroll
    for (int i = 0; i < RM; i++) {
        int gm = bm + ty * RM + i;
        if (gm >= M) continue;
#pragma unroll
        for (int j = 0; j < 4; j++) {
            unsigned int lo, hi;
            asm("mov.b64 {%0, %1}, %2;" : "=r"(lo), "=r"(hi) : "l"(acc[i][j]));
            float vx = __uint_as_float(lo), vy = __uint_as_float(hi);
            int gn = bn + tx * 8 + 2 * j;
            if (BIAS_RELU) { vx = fmaxf(vx + bias[gn], 0.0f); vy = fmaxf(vy + bias[gn + 1], 0.0f); }
            *(float2*)(C + (size_t)gm * Nc + gn) = make_float2(vx, vy);
        }
    }
}

// ---------------- fused GCN aggregation (CSR gather; F=256) ----------------
// out = [relu](in[n]*dis^2 + sum in[src]*norm [+bias]); OUTBF16 -> g_bh/g_bl split
template <bool BIAS_RELU, bool OUTBF16>
__global__ void k_agg256(int in_sel, const float* __restrict__ bias) {
    int w = (blockIdx.x * blockDim.x + threadIdx.x) >> 5;
    int lane = threadIdx.x & 31;
    if (w >= NN) return;
    const float4* h4 = (const float4*)selbuf(in_sel);
    float ds = g_dis[w];
    float self = ds * ds;
    float4 acc[2];
#pragma unroll
    for (int j = 0; j < 2; j++) {
        float4 v = h4[(size_t)w * 64 + j * 32 + lane];
        acc[j] = make_float4(v.x * self, v.y * self, v.z * self, v.w * self);
    }
    int rbeg = g_rowptr[w], rend = g_rowptr[w + 1];
    for (int e = rbeg; e < rend; e++) {
        int s = g_csrc[e];
        float nm = g_cnorm[e];
#pragma unroll
        for (int j = 0; j < 2; j++) {
            float4 v = h4[(size_t)s * 64 + j * 32 + lane];
            acc[j].x += v.x * nm; acc[j].y += v.y * nm;
            acc[j].z += v.z * nm; acc[j].w += v.w * nm;
        }
    }
#pragma unroll
    for (int j = 0; j < 2; j++) {
        float4 o = acc[j];
        if (BIAS_RELU) {
            float4 b = ((const float4*)bias)[j * 32 + lane];
            o.x = fmaxf(o.x + b.x, 0.0f); o.y = fmaxf(o.y + b.y, 0.0f);
            o.z = fmaxf(o.z + b.z, 0.0f); o.w = fmaxf(o.w + b.w, 0.0f);
        }
        if (OUTBF16) {
            float f[4] = {o.x, o.y, o.z, o.w};
            unsigned int ph[2], pl[2];
#pragma unroll
            for (int q = 0; q < 2; q++) {
                __nv_bfloat16 h0 = __float2bfloat16(f[2*q]);
                __nv_bfloat16 h1 = __float2bfloat16(f[2*q+1]);
                __nv_bfloat16 l0 = __float2bfloat16(f[2*q]   - __bfloat162float(h0));
                __nv_bfloat16 l1 = __float2bfloat16(f[2*q+1] - __bfloat162float(h1));
                ph[q] = (unsigned int)__bfloat16_as_ushort(h0) | ((unsigned int)__bfloat16_as_ushort(h1) << 16);
                pl[q] = (unsigned int)__bfloat16_as_ushort(l0) | ((unsigned int)__bfloat16_as_ushort(l1) << 16);
            }
            size_t off = (size_t)w * 256 + j * 128 + lane * 4;
            *(uint2*)(g_bh + off) = make_uint2(ph[0], ph[1]);
            *(uint2*)(g_bl + off) = make_uint2(pl[0], pl[1]);
        } else {
            ((float4*)g_x)[(size_t)w * 64 + j * 32 + lane] = o;
        }
    }
}

// ---------------- pooling ----------------
__global__ void k_gate(const float* __restrict__ pw, const float* __restrict__ pb) {
    int warp = (blockIdx.x * blockDim.x + threadIdx.x) >> 5;
    int lane = threadIdx.x & 31;
    if (warp >= NN) return;
    const float* row = g_x + (size_t)warp * H3;
    float sum = 0.0f;
#pragma unroll
    for (int f = lane; f < H3; f += 32) sum += row[f] * pw[f];
#pragma unroll
    for (int off = 16; off > 0; off >>= 1) sum += __shfl_down_sync(0xFFFFFFFFu, sum, off);
    if (lane == 0) g_gate[warp] = 1.0f / (1.0f + expf(-(sum + pb[0])));
}
__global__ void k_poolg() {
    int g = blockIdx.x, t = threadIdx.x;
    int nbeg = g_gptr[g], nend = g_gptr[g + 1];
    const float4* x4 = (const float4*)g_x;
    float4 s = make_float4(0.f, 0.f, 0.f, 0.f);
    float4 m = make_float4(0.f, 0.f, 0.f, 0.f);
    for (int n = nbeg; n < nend; n++) {
        float gt = g_gate[n];
        float4 v = x4[(size_t)n * 128 + t];
        s.x += v.x * gt; s.y += v.y * gt; s.z += v.z * gt; s.w += v.w * gt;
        m.x = fmaxf(m.x, v.x); m.y = fmaxf(m.y, v.y);
        m.z = fmaxf(m.z, v.z); m.w = fmaxf(m.w, v.w);
    }
    float4* f4 = (float4*)g_feats;
    f4[(size_t)g * 256 + t] = s;
    f4[(size_t)g * 256 + 128 + t] = m;
}

// ---------------- launch ----------------
static inline unsigned cdiv(int a, int b) { return (unsigned)((a + b - 1) / b); }

extern "C" void kernel_launch(void* const* d_in, const int* in_sizes, int n_in,
                              void* d_out, int out_size) {
    int iNF=-1,iEI=-1,iB=-1,iW1=-1,iW2=-1,iW3=-1,iWo=-1;
    int ib1=-1,ib2=-1,ib3=-1,ipw=-1,ipb=-1,ibo=-1;
    for (int i = 0; i < n_in; i++) {
        int s = in_sizes[i];
        if      (s == NN*FIN)     iNF = i;
        else if (s == 2*EE)       iEI = i;
        else if (s == NN)         iB  = i;
        else if (s == FIN*H1)     { if (iW1 < 0) iW1 = i; else iW2 = i; }
        else if (s == H2*H3)      iW3 = i;
        else if (s == 2*H3*FP)    iWo = i;
        else if (s == H1)         { if (ib1 < 0) ib1 = i; else ib2 = i; }
        else if (s == H3)         { if (ib3 < 0) ib3 = i; else ipw = i; }
        else if (s == 1)          ipb = i;
        else if (s == FP)         ibo = i;
    }
    const float* x0    = (const float*)d_in[iNF];
    const void*  ei    = d_in[iEI];
    const void*  batch = d_in[iB];
    const float* W1 = (const float*)d_in[iW1];
    const float* b1 = (const float*)d_in[ib1];
    const float* W2 = (const float*)d_in[iW2];
    const float* b2 = (const float*)d_in[ib2];
    const float* W3 = (const float*)d_in[iW3];
    const float* b3 = (const float*)d_in[ib3];
    const float* pw = (const float*)d_in[ipw];
    const float* pb = (const float*)d_in[ipb];
    const float* Wo = (const float*)d_in[iWo];
    const float* bo = (const float*)d_in[ibo];
    float* out = (float*)d_out;

    const int TB = 256;
    const int AGG_G = cdiv(NN * 32, TB);
    const int MT = cdiv(NN, 128);     // 391

    // 0-2: bf16 setup (GEMM1 prerequisites)
    k_detect<<<1, 32>>>(ei, batch);                    // 0
    k_xsplit<<<cdiv(NN * FIN, TB), TB>>>(x0);          // 1
    k_wstack<<<cdiv(262144, TB), TB>>>(W1, W2, W3);    // 2

    // 3: layer-1 GEMM (wmma bf16x3, 64x64 warp tiles) -> g_h  — ncu capture slot
    {
        dim3 grid(H1 / 128, MT);
        wgemm<<<grid, 128>>>(1, 1, NN, H1);
    }

    // 4-10: CSR + graph ranges
    k_zero_cnt<<<cdiv(NN, TB), TB>>>();
    k_decode_hist<<<cdiv(EE, TB), TB>>>(ei, batch);
    k_scanA<<<NPART, 512>>>();
    k_scanB<<<1, 128>>>();
    k_scanC<<<cdiv(NN, TB), TB>>>();
    k_norm_fill<<<cdiv(EE, TB), TB>>>();
    k_gscan<<<1, GG>>>();

    // layer 1 aggregation: g_h -> bf16 split (bias+relu)
    k_agg256<true, true><<<AGG_G, TB>>>(1, b1);

    // layer 2: GEMM -> g_h; agg -> fp32 g_x (agg3's gather source)
    {
        dim3 grid(H2 / 128, MT);
        wgemm<<<grid, 128>>>(2, 1, NN, H2);
    }
    k_agg256<true, false><<<AGG_G, TB>>>(1, b2);

    // layer 3 (commuted): agg g_x -> bf16 split (no bias), GEMM -> g_x, epilogue
    k_agg256<false, true><<<AGG_G, TB>>>(0, nullptr);
    {
        dim3 grid(H3 / 128, MT);
        wgemm<<<grid, 128>>>(3, 0, NN, H3);
    }
    k_bias_relu<<<cdiv(NN * H3, TB), TB>>>(b3);

    // pooling
    k_gate<<<cdiv(NN * 32, TB), TB>>>(pw, pb);
    k_poolg<<<GG, 128>>>();

    // head: fp32 f32x2 path
    {
        dim3 grid(FP / TBN, cdiv(GG, 64));
        sgemm128<64, true><<<grid, 256>>>(nullptr, 2, Wo, bo, out, -1, GG, 2 * H3, FP);
    }
}

// round 16
// speedup vs baseline: 1.0944x; 1.0944x over previous
#include <cuda_runtime.h>
#include <cuda_bf16.h>
#include <mma.h>
#include <cstdint>

using namespace nvcuda;

// Problem constants
#define NN 50000
#define EE 800000
#define FIN 256
#define H1 256
#define H2 256
#define H3 512
#define GG 512
#define FP 2048
#define NPART 98         // ceil(NN/512)

// ---------------- device scratch ----------------
__device__ float g_x[NN * H3];
__device__ float g_h[NN * H3];
__device__ float g_feats[GG * 2 * H3];
__device__ float g_dis[NN];
__device__ float g_gate[NN];
__device__ int   g_s32[EE];
__device__ int   g_d32[EE];
__device__ int   g_bat[NN];
__device__ int   g_ei_is64;
__device__ int   g_b_is64;
__device__ int   g_rowptr[NN + 1];
__device__ int   g_cursor[NN];
__device__ int   g_ecnt[NN];
__device__ int   g_tmp[NN];
__device__ int   g_part[128];
__device__ int   g_csrc[EE];
__device__ float g_cnorm[EE];
__device__ int   g_gcnt[GG];
__device__ int   g_gptr[GG + 1];
// bf16 hi/lo split of the current GEMM input (K=256 always)
__device__ __nv_bfloat16 g_bh[NN * FIN];
__device__ __nv_bfloat16 g_bl[NN * FIN];
// stacked split weights: rows [0,256)=Wh, [256,512)=Wl, [512,768)=Wh
__device__ __nv_bfloat16 g_wst1[768 * H1];
__device__ __nv_bfloat16 g_wst2[768 * H2];
__device__ __nv_bfloat16 g_wst3[768 * H3];

__device__ __forceinline__ float* selbuf(int s) {
    switch (s) { case 0: return g_x; case 1: return g_h; default: return g_feats; }
}
__device__ __forceinline__ const __nv_bfloat16* selwst(int s) {
    switch (s) { case 1: return g_wst1; case 2: return g_wst2; default: return g_wst3; }
}
__device__ __forceinline__ int clampi(int v, int lo, int hi) {
    return v < lo ? lo : (v > hi ? hi : v);
}

// ---------------- dtype detection ----------------
__global__ void k_detect(const void* ei, const void* batch) {
    if (threadIdx.x != 0 || blockIdx.x != 0) return;
    const long long* e64 = (const long long*)ei;
    int ok = 1;
    for (int i = 0; i < 16; i++) { long long v = e64[i]; if (v < 0 || v >= NN) ok = 0; }
    g_ei_is64 = ok;
    const long long* b64 = (const long long*)batch;
    int okb = 1;
    for (int i = 0; i < 16; i++) { long long v = b64[NN/2 - 16 + i]; if (v < 0 || v >= GG) okb = 0; }
    g_b_is64 = okb;
}
__device__ __forceinline__ int load_edge(const void* ei, int idx) {
    if (g_ei_is64) return clampi((int)((const long long*)ei)[idx], 0, NN - 1);
    return clampi(((const int*)ei)[idx], 0, NN - 1);
}

// ---------------- bf16 split setup ----------------
__global__ void k_xsplit(const float* __restrict__ x0) {
    int i = blockIdx.x * blockDim.x + threadIdx.x;
    if (i >= NN * FIN) return;
    float x = x0[i];
    __nv_bfloat16 h = __float2bfloat16(x);
    g_bh[i] = h;
    g_bl[i] = __float2bfloat16(x - __bfloat162float(h));
}
__global__ void k_wstack(const float* __restrict__ W1, const float* __restrict__ W2,
                         const float* __restrict__ W3) {
    int i = blockIdx.x * blockDim.x + threadIdx.x;
    const float* W; __nv_bfloat16* D; int Nc;
    if (i < 65536)       { W = W1; D = g_wst1; Nc = H1; }
    else if (i < 131072) { W = W2; D = g_wst2; Nc = H2; i -= 65536; }
    else if (i < 262144) { W = W3; D = g_wst3; Nc = H3; i -= 131072; }
    else return;
    int k = i / Nc, n = i % Nc;
    float x = W[(size_t)k * Nc + n];
    __nv_bfloat16 h = __float2bfloat16(x);
    __nv_bfloat16 l = __float2bfloat16(x - __bfloat162float(h));
    D[(size_t)k * Nc + n] = h;
    D[(size_t)(256 + k) * Nc + n] = l;
    D[(size_t)(512 + k) * Nc + n] = h;
}

// ---------------- precompute ----------------
__global__ void k_zero_cnt() {
    int i = blockIdx.x * blockDim.x + threadIdx.x;
    if (i < NN) g_ecnt[i] = 0;
    if (i < GG) g_gcnt[i] = 0;
}
__global__ void k_decode_hist(const void* ei, const void* batch) {
    int i = blockIdx.x * blockDim.x + threadIdx.x;
    if (i < EE) {
        int s = load_edge(ei, i);
        int d = load_edge(ei, EE + i);
        g_s32[i] = s;
        g_d32[i] = d;
        atomicAdd(&g_ecnt[d], 1);
    }
    if (i < NN) {
        int g = g_b_is64 ? (int)((const long long*)batch)[i] : ((const int*)batch)[i];
        g = clampi(g, 0, GG - 1);
        g_bat[i] = g;
        atomicAdd(&g_gcnt[g], 1);
    }
}
__global__ void k_scanA() {
    __shared__ int wsum[16];
    int b = blockIdx.x, t = threadIdx.x;
    int i = b * 512 + t;
    int v = (i < NN) ? g_ecnt[i] : 0;
    int lane = t & 31, wid = t >> 5;
    int x = v;
#pragma unroll
    for (int o = 1; o < 32; o <<= 1) { int y = __shfl_up_sync(~0u, x, o); if (lane >= o) x += y; }
    if (lane == 31) wsum[wid] = x;
    __syncthreads();
    if (wid == 0) {
        int s = (lane < 16) ? wsum[lane] : 0;
#pragma unroll
        for (int o = 1; o < 16; o <<= 1) { int y = __shfl_up_sync(~0u, s, o); if (lane >= o) s += y; }
        if (lane < 16) wsum[lane] = s;
    }
    __syncthreads();
    int incl = x + (wid ? wsum[wid - 1] : 0);
    if (i < NN) g_tmp[i] = incl;
    if (t == 511) g_part[b] = incl;
}
__global__ void k_scanB() {
    __shared__ int ws[4];
    int t = threadIdx.x;
    int v = (t < NPART) ? g_part[t] : 0;
    int lane = t & 31, wid = t >> 5;
    int x = v;
#pragma unroll
    for (int o = 1; o < 32; o <<= 1) { int y = __shfl_up_sync(~0u, x, o); if (lane >= o) x += y; }
    if (lane == 31) ws[wid] = x;
    __syncthreads();
    if (t == 0) { int a = 0; for (int w = 0; w < 4; w++) { int tm = ws[w]; ws[w] = a; a += tm; } }
    __syncthreads();
    x += ws[wid];
    if (t < NPART) g_part[t] = x - v;
}
__global__ void k_scanC() {
    int i = blockIdx.x * blockDim.x + threadIdx.x;
    if (i >= NN) return;
    int incl = g_tmp[i] + g_part[i >> 9];
    g_rowptr[i + 1] = incl;
    int cnt = g_ecnt[i];
    g_cursor[i] = incl - cnt;
    if (i == 0) g_rowptr[0] = 0;
    g_dis[i] = rsqrtf((float)(cnt + 1));
}
__global__ void k_norm_fill() {
    int e = blockIdx.x * blockDim.x + threadIdx.x;
    if (e >= EE) return;
    int s = g_s32[e], d = g_d32[e];
    int pos = atomicAdd(&g_cursor[d], 1);
    g_csrc[pos] = s;
    g_cnorm[pos] = g_dis[s] * g_dis[d];
}
__global__ void k_gscan() {
    __shared__ int sh[GG];
    int tid = threadIdx.x;
    sh[tid] = g_gcnt[tid];
    __syncthreads();
    for (int off = 1; off < GG; off <<= 1) {
        int t = (tid >= off) ? sh[tid - off] : 0;
        __syncthreads();
        sh[tid] += t;
        __syncthreads();
    }
    g_gptr[tid + 1] = sh[tid];
    if (tid == 0) g_gptr[0] = 0;
}

// ---------------- wmma bf16x3 GEMM (conflict-free pads) ----------------
// C[M,Nc] fp32 = split-K: [Ah|Ah|Al](M x 768) @ [Wh;Wl;Wh](768 x Nc),
// dropping Al*Wl (error ~2^-16 relative).
// 128x128 block tile, BK=32, 256 threads (8 warps, 2x4), warp tile 64x32.
// Pads chosen so consecutive rows hit distinct 16B smem granules:
//   ALD=40 (80B row; 80/16=5, 5r mod 8 covers all 8) — conflict-free
//   BLD=136 (272B row; 17r mod 8 covers all 8)       — conflict-free
#define ALD 40
#define BLD 136

__global__ void __launch_bounds__(256)
wgemm(int w_sel, int c_sel, int M, int Nc) {
    const __nv_bfloat16* Wst = selwst(w_sel);
    float* C = selbuf(c_sel);
    __shared__ __nv_bfloat16 As[2][128][ALD];
    __shared__ __nv_bfloat16 Bs[2][32][BLD];
    const int tid = threadIdx.x;
    const int wid = tid >> 5;
    const int wm = wid & 1, wn = wid >> 1;     // 2 x 4 warp grid, 64x32 each
    const int bm = blockIdx.y * 128, bn = blockIdx.x * 128;

    wmma::fragment<wmma::accumulator, 16, 16, 16, float> acc[4][2];
#pragma unroll
    for (int mi = 0; mi < 4; mi++)
#pragma unroll
        for (int ni = 0; ni < 2; ni++) wmma::fill_fragment(acc[mi][ni], 0.0f);

    // A: 128 rows x 32 cols; thread -> row=tid>>1, 16-elem chunk=(tid&1)*16,
    // two uint4 per chunk.
    const int ar = tid >> 1, ac = (tid & 1) * 16;
    // B: 32 rows x 128 cols; thread -> row=tid>>3, 16-elem chunk=(tid&7)*16.
    const int wr = tid >> 3, wc = (tid & 7) * 16;
    const int gm = bm + ar;

    auto load_tiles = [&](int b, int kb) {
        // kb<16 -> Ah (vs Wh then Wl), kb>=16 -> Al (vs Wh). A col = (kb&7)*32.
        const __nv_bfloat16* Asrc = (kb < 16) ? g_bh : g_bl;
        int ka = (kb & 7) * 32;
        uint4 av0 = make_uint4(0u, 0u, 0u, 0u);
        uint4 av1 = make_uint4(0u, 0u, 0u, 0u);
        if (gm < M) {
            const __nv_bfloat16* ap = Asrc + (size_t)gm * FIN + ka + ac;
            av0 = *(const uint4*)ap;
            av1 = *(const uint4*)(ap + 8);
        }
        *(uint4*)&As[b][ar][ac] = av0;
        *(uint4*)&As[b][ar][ac + 8] = av1;
        const __nv_bfloat16* wp = Wst + (size_t)(kb * 32 + wr) * Nc + bn + wc;
        *(uint4*)&Bs[b][wr][wc] = *(const uint4*)wp;
        *(uint4*)&Bs[b][wr][wc + 8] = *(const uint4*)(wp + 8);
    };

    load_tiles(0, 0);
    __syncthreads();

#pragma unroll 1
    for (int kb = 0; kb < 24; kb++) {
        int b = kb & 1;
        if (kb + 1 < 24) load_tiles((kb + 1) & 1, kb + 1);
#pragma unroll
        for (int ki = 0; ki < 2; ki++) {
            wmma::fragment<wmma::matrix_a, 16, 16, 16, __nv_bfloat16, wmma::row_major> af[4];
            wmma::fragment<wmma::matrix_b, 16, 16, 16, __nv_bfloat16, wmma::row_major> bfr[2];
#pragma unroll
            for (int mi = 0; mi < 4; mi++)
                wmma::load_matrix_sync(af[mi], &As[b][wm * 64 + mi * 16][ki * 16], ALD);
#pragma unroll
            for (int ni = 0; ni < 2; ni++)
                wmma::load_matrix_sync(bfr[ni], &Bs[b][ki * 16][wn * 32 + ni * 16], BLD);
#pragma unroll
            for (int mi = 0; mi < 4; mi++)
#pragma unroll
                for (int ni = 0; ni < 2; ni++)
                    wmma::mma_sync(acc[mi][ni], af[mi], bfr[ni], acc[mi][ni]);
        }
        __syncthreads();
    }

#pragma unroll
    for (int mi = 0; mi < 4; mi++) {
        int row = bm + wm * 64 + mi * 16;
        if (row + 16 > M) continue;     // M % 16 == 0 -> frag-granular guard exact
#pragma unroll
        for (int ni = 0; ni < 2; ni++) {
            int col = bn + wn * 32 + ni * 16;
            wmma::store_matrix_sync(C + (size_t)row * Nc + col, acc[mi][ni], Nc,
                                    wmma::mem_row_major);
        }
    }
}

// g_x = relu(g_x + b)  (post-GEMM3 epilogue)
__global__ void k_bias_relu(const float* __restrict__ b) {
    int i = blockIdx.x * blockDim.x + threadIdx.x;
    if (i < NN * H3) g_x[i] = fmaxf(g_x[i] + b[i & (H3 - 1)], 0.0f);
}

// ---------------- fp32 SGEMM (head) with fma.rn.f32x2 ----------------
#define TBN 128
#define TBK 16
template <int BMv, bool BIAS_RELU>
__global__ void __launch_bounds__(256)
sgemm128(const float* __restrict__ Aext, int a_sel,
         const float* __restrict__ W, const float* __restrict__ bias,
         float* __restrict__ Cext, int c_sel, int M, int K, int Nc) {
    constexpr int RM = BMv / 16;
    constexpr int AL = BMv / 64;
    const float* A = (a_sel < 0) ? Aext : selbuf(a_sel);
    float* C = (c_sel < 0) ? Cext : selbuf(c_sel);
    __shared__ float As2[TBK][BMv + 4];
    __shared__ float Ws2[TBK][TBN + 4];
    const int tid = threadIdx.x;
    const int tx = tid & 15, ty = tid >> 4;
    const int bm = blockIdx.y * BMv, bn = blockIdx.x * TBN;
    float4 pa[AL], pw[2];
    unsigned long long acc[RM][4];
#pragma unroll
    for (int i = 0; i < RM; i++)
#pragma unroll
        for (int j = 0; j < 4; j++) acc[i][j] = 0ull;
#pragma unroll
    for (int i = 0; i < AL; i++) {
        int idx = tid + i * 256;
        int m = idx >> 2, kq = idx & 3;
        int gm = bm + m;
        pa[i] = (gm < M) ? *(const float4*)(A + (size_t)gm * K + kq * 4)
                         : make_float4(0.f, 0.f, 0.f, 0.f);
    }
#pragma unroll
    for (int i = 0; i < 2; i++) {
        int idx = tid + i * 256;
        int kk = idx >> 5, nq = idx & 31;
        pw[i] = *(const float4*)(W + (size_t)kk * Nc + bn + nq * 4);
    }
    for (int k0 = 0; k0 < K; k0 += TBK) {
#pragma unroll
        for (int i = 0; i < AL; i++) {
            int idx = tid + i * 256;
            int m = idx >> 2, kq = idx & 3;
            As2[kq * 4 + 0][m] = pa[i].x; As2[kq * 4 + 1][m] = pa[i].y;
            As2[kq * 4 + 2][m] = pa[i].z; As2[kq * 4 + 3][m] = pa[i].w;
        }
#pragma unroll
        for (int i = 0; i < 2; i++) {
            int idx = tid + i * 256;
            int kk = idx >> 5, nq = idx & 31;
            *(float4*)&Ws2[kk][nq * 4] = pw[i];
        }
        __syncthreads();
        if (k0 + TBK < K) {
            int k1 = k0 + TBK;
#pragma unroll
            for (int i = 0; i < AL; i++) {
                int idx = tid + i * 256;
                int m = idx >> 2, kq = idx & 3;
                int gm = bm + m;
                pa[i] = (gm < M) ? *(const float4*)(A + (size_t)gm * K + k1 + kq * 4)
                                 : make_float4(0.f, 0.f, 0.f, 0.f);
            }
#pragma unroll
            for (int i = 0; i < 2; i++) {
                int idx = tid + i * 256;
                int kk = idx >> 5, nq = idx & 31;
                pw[i] = *(const float4*)(W + (size_t)(k1 + kk) * Nc + bn + nq * 4);
            }
        }
#pragma unroll
        for (int kk = 0; kk < TBK; kk++) {
            float a8[RM];
#pragma unroll
            for (int q = 0; q < RM / 4; q++) {
                float4 af = *(const float4*)&As2[kk][ty * RM + q * 4];
                a8[q * 4 + 0] = af.x; a8[q * 4 + 1] = af.y;
                a8[q * 4 + 2] = af.z; a8[q * 4 + 3] = af.w;
            }
            unsigned long long a2[RM];
#pragma unroll
            for (int i = 0; i < RM; i++) {
                unsigned int ab = __float_as_uint(a8[i]);
                asm("mov.b64 %0, {%1, %1};" : "=l"(a2[i]) : "r"(ab));
            }
            float4 wf0 = *(const float4*)&Ws2[kk][tx * 8];
            float4 wf1 = *(const float4*)&Ws2[kk][tx * 8 + 4];
            unsigned long long w2[4];
            asm("mov.b64 %0, {%1, %2};" : "=l"(w2[0]) : "r"(__float_as_uint(wf0.x)), "r"(__float_as_uint(wf0.y)));
            asm("mov.b64 %0, {%1, %2};" : "=l"(w2[1]) : "r"(__float_as_uint(wf0.z)), "r"(__float_as_uint(wf0.w)));
            asm("mov.b64 %0, {%1, %2};" : "=l"(w2[2]) : "r"(__float_as_uint(wf1.x)), "r"(__float_as_uint(wf1.y)));
            asm("mov.b64 %0, {%1, %2};" : "=l"(w2[3]) : "r"(__float_as_uint(wf1.z)), "r"(__float_as_uint(wf1.w)));
#pragma unroll
            for (int i = 0; i < RM; i++)
#pragma unroll
                for (int j = 0; j < 4; j++)
                    asm("fma.rn.f32x2 %0, %1, %2, %3;"
                        : "=l"(acc[i][j]) : "l"(a2[i]), "l"(w2[j]), "l"(acc[i][j]));
        }
        __syncthreads();
    }
#pragma unroll
    for (int i = 0; i < RM; i++) {
        int gm = bm + ty * RM + i;
        if (gm >= M) continue;
#pragma unroll
        for (int j = 0; j < 4; j++) {
            unsigned int lo, hi;
            asm("mov.b64 {%0, %1}, %2;" : "=r"(lo), "=r"(hi) : "l"(acc[i][j]));
            float vx = __uint_as_float(lo), vy = __uint_as_float(hi);
            int gn = bn + tx * 8 + 2 * j;
            if (BIAS_RELU) { vx = fmaxf(vx + bias[gn], 0.0f); vy = fmaxf(vy + bias[gn + 1], 0.0f); }
            *(float2*)(C + (size_t)gm * Nc + gn) = make_float2(vx, vy);
        }
    }
}

// ---------------- fused GCN aggregation (CSR gather; F=256) ----------------
// out = [relu](in[n]*dis^2 + sum in[src]*norm [+bias]); OUTBF16 -> g_bh/g_bl split
template <bool BIAS_RELU, bool OUTBF16>
__global__ void k_agg256(int in_sel, const float* __restrict__ bias) {
    int w = (blockIdx.x * blockDim.x + threadIdx.x) >> 5;
    int lane = threadIdx.x & 31;
    if (w >= NN) return;
    const float4* h4 = (const float4*)selbuf(in_sel);
    float ds = g_dis[w];
    float self = ds * ds;
    float4 acc[2];
#pragma unroll
    for (int j = 0; j < 2; j++) {
        float4 v = h4[(size_t)w * 64 + j * 32 + lane];
        acc[j] = make_float4(v.x * self, v.y * self, v.z * self, v.w * self);
    }
    int rbeg = g_rowptr[w], rend = g_rowptr[w + 1];
    for (int e = rbeg; e < rend; e++) {
        int s = g_csrc[e];
        float nm = g_cnorm[e];
#pragma unroll
        for (int j = 0; j < 2; j++) {
            float4 v = h4[(size_t)s * 64 + j * 32 + lane];
            acc[j].x += v.x * nm; acc[j].y += v.y * nm;
            acc[j].z += v.z * nm; acc[j].w += v.w * nm;
        }
    }
#pragma unroll
    for (int j = 0; j < 2; j++) {
        float4 o = acc[j];
        if (BIAS_RELU) {
            float4 b = ((const float4*)bias)[j * 32 + lane];
            o.x = fmaxf(o.x + b.x, 0.0f); o.y = fmaxf(o.y + b.y, 0.0f);
            o.z = fmaxf(o.z + b.z, 0.0f); o.w = fmaxf(o.w + b.w, 0.0f);
        }
        if (OUTBF16) {
            float f[4] = {o.x, o.y, o.z, o.w};
            unsigned int ph[2], pl[2];
#pragma unroll
            for (int q = 0; q < 2; q++) {
                __nv_bfloat16 h0 = __float2bfloat16(f[2*q]);
                __nv_bfloat16 h1 = __float2bfloat16(f[2*q+1]);
                __nv_bfloat16 l0 = __float2bfloat16(f[2*q]   - __bfloat162float(h0));
                __nv_bfloat16 l1 = __float2bfloat16(f[2*q+1] - __bfloat162float(h1));
                ph[q] = (unsigned int)__bfloat16_as_ushort(h0) | ((unsigned int)__bfloat16_as_ushort(h1) << 16);
                pl[q] = (unsigned int)__bfloat16_as_ushort(l0) | ((unsigned int)__bfloat16_as_ushort(l1) << 16);
            }
            size_t off = (size_t)w * 256 + j * 128 + lane * 4;
            *(uint2*)(g_bh + off) = make_uint2(ph[0], ph[1]);
            *(uint2*)(g_bl + off) = make_uint2(pl[0], pl[1]);
        } else {
            ((float4*)g_x)[(size_t)w * 64 + j * 32 + lane] = o;
        }
    }
}

// ---------------- pooling ----------------
__global__ void k_gate(const float* __restrict__ pw, const float* __restrict__ pb) {
    int warp = (blockIdx.x * blockDim.x + threadIdx.x) >> 5;
    int lane = threadIdx.x & 31;
    if (warp >= NN) return;
    const float* row = g_x + (size_t)warp * H3;
    float sum = 0.0f;
#pragma unroll
    for (int f = lane; f < H3; f += 32) sum += row[f] * pw[f];
#pragma unroll
    for (int off = 16; off > 0; off >>= 1) sum += __shfl_down_sync(0xFFFFFFFFu, sum, off);
    if (lane == 0) g_gate[warp] = 1.0f / (1.0f + expf(-(sum + pb[0])));
}
__global__ void k_poolg() {
    int g = blockIdx.x, t = threadIdx.x;
    int nbeg = g_gptr[g], nend = g_gptr[g + 1];
    const float4* x4 = (const float4*)g_x;
    float4 s = make_float4(0.f, 0.f, 0.f, 0.f);
    float4 m = make_float4(0.f, 0.f, 0.f, 0.f);
    for (int n = nbeg; n < nend; n++) {
        float gt = g_gate[n];
        float4 v = x4[(size_t)n * 128 + t];
        s.x += v.x * gt; s.y += v.y * gt; s.z += v.z * gt; s.w += v.w * gt;
        m.x = fmaxf(m.x, v.x); m.y = fmaxf(m.y, v.y);
        m.z = fmaxf(m.z, v.z); m.w = fmaxf(m.w, v.w);
    }
    float4* f4 = (float4*)g_feats;
    f4[(size_t)g * 256 + t] = s;
    f4[(size_t)g * 256 + 128 + t] = m;
}

// ---------------- launch ----------------
static inline unsigned cdiv(int a, int b) { return (unsigned)((a + b - 1) / b); }

extern "C" void kernel_launch(void* const* d_in, const int* in_sizes, int n_in,
                              void* d_out, int out_size) {
    int iNF=-1,iEI=-1,iB=-1,iW1=-1,iW2=-1,iW3=-1,iWo=-1;
    int ib1=-1,ib2=-1,ib3=-1,ipw=-1,ipb=-1,ibo=-1;
    for (int i = 0; i < n_in; i++) {
        int s = in_sizes[i];
        if      (s == NN*FIN)     iNF = i;
        else if (s == 2*EE)       iEI = i;
        else if (s == NN)         iB  = i;
        else if (s == FIN*H1)     { if (iW1 < 0) iW1 = i; else iW2 = i; }
        else if (s == H2*H3)      iW3 = i;
        else if (s == 2*H3*FP)    iWo = i;
        else if (s == H1)         { if (ib1 < 0) ib1 = i; else ib2 = i; }
        else if (s == H3)         { if (ib3 < 0) ib3 = i; else ipw = i; }
        else if (s == 1)          ipb = i;
        else if (s == FP)         ibo = i;
    }
    const float* x0    = (const float*)d_in[iNF];
    const void*  ei    = d_in[iEI];
    const void*  batch = d_in[iB];
    const float* W1 = (const float*)d_in[iW1];
    const float* b1 = (const float*)d_in[ib1];
    const float* W2 = (const float*)d_in[iW2];
    const float* b2 = (const float*)d_in[ib2];
    const float* W3 = (const float*)d_in[iW3];
    const float* b3 = (const float*)d_in[ib3];
    const float* pw = (const float*)d_in[ipw];
    const float* pb = (const float*)d_in[ipb];
    const float* Wo = (const float*)d_in[iWo];
    const float* bo = (const float*)d_in[ibo];
    float* out = (float*)d_out;

    const int TB = 256;
    const int AGG_G = cdiv(NN * 32, TB);
    const int MT = cdiv(NN, 128);     // 391

    // 0-2: bf16 setup (GEMM1 prerequisites)
    k_detect<<<1, 32>>>(ei, batch);                    // 0
    k_xsplit<<<cdiv(NN * FIN, TB), TB>>>(x0);          // 1
    k_wstack<<<cdiv(262144, TB), TB>>>(W1, W2, W3);    // 2

    // 3: layer-1 GEMM (wmma bf16x3, conflict-free pads) -> g_h — ncu capture slot
    {
        dim3 grid(H1 / 128, MT);
        wgemm<<<grid, 256>>>(1, 1, NN, H1);
    }

    // 4-10: CSR + graph ranges
    k_zero_cnt<<<cdiv(NN, TB), TB>>>();
    k_decode_hist<<<cdiv(EE, TB), TB>>>(ei, batch);
    k_scanA<<<NPART, 512>>>();
    k_scanB<<<1, 128>>>();
    k_scanC<<<cdiv(NN, TB), TB>>>();
    k_norm_fill<<<cdiv(EE, TB), TB>>>();
    k_gscan<<<1, GG>>>();

    // layer 1 aggregation: g_h -> bf16 split (bias+relu)
    k_agg256<true, true><<<AGG_G, TB>>>(1, b1);

    // layer 2: GEMM -> g_h; agg -> fp32 g_x (agg3's gather source)
    {
        dim3 grid(H2 / 128, MT);
        wgemm<<<grid, 256>>>(2, 1, NN, H2);
    }
    k_agg256<true, false><<<AGG_G, TB>>>(1, b2);

    // layer 3 (commuted): agg g_x -> bf16 split (no bias), GEMM -> g_x, epilogue
    k_agg256<false, true><<<AGG_G, TB>>>(0, nullptr);
    {
        dim3 grid(H3 / 128, MT);
        wgemm<<<grid, 256>>>(3, 0, NN, H3);
    }
    k_bias_relu<<<cdiv(NN * H3, TB), TB>>>(b3);

    // pooling
    k_gate<<<cdiv(NN * 32, TB), TB>>>(pw, pb);
    k_poolg<<<GG, 128>>>();

    // head: fp32 f32x2 path
    {
        dim3 grid(FP / TBN, cdiv(GG, 64));
        sgemm128<64, true><<<grid, 256>>>(nullptr, 2, Wo, bo, out, -1, GG, 2 * H3, FP);
    }
}